// round 2
// baseline (speedup 1.0000x reference)
#include <cuda_runtime.h>
#include <cstdint>

#define N_NODES 50000
#define N_EDGES 600000
#define NFEAT   7
#define EFEAT   4
#define H       128
#define L_LAYERS 4
#define K_HOPS   3

// ---------------- scratch (static device globals; no allocation) -------------
__device__ float g_hsum[N_NODES * H];
__device__ float g_bufA[N_NODES * H];
__device__ float g_bufB[N_NODES * H];
__device__ float g_p0[N_NODES * H];
__device__ float g_p1[N_NODES * H];
__device__ int   g_deg[N_NODES];
__device__ float g_dinv[N_NODES];
__device__ int   g_ptr[N_NODES + 1];
__device__ int   g_cur[N_NODES];
__device__ int   g_srcs[N_EDGES];
__device__ int   g_eids[N_EDGES];
__device__ float g_normv[N_EDGES];

// ---------------- flags for GEMM epilogue ----------------
#define FLAG_ACCUM    1
#define FLAG_RELU     2
#define FLAG_BIAS     4
#define FLAG_DEGSCALE 8

// ============================================================================
// Kernel 1: zero deg + cursor
// ============================================================================
__global__ void k_init() {
    int i = blockIdx.x * blockDim.x + threadIdx.x;
    if (i < N_NODES) { g_deg[i] = 0; g_cur[i] = 0; }
}

// ============================================================================
// Kernel 2: degree histogram at target (col)
// ============================================================================
__global__ void k_count(const int* __restrict__ ei) {
    int e = blockIdx.x * blockDim.x + threadIdx.x;
    if (e < N_EDGES) {
        int c = ei[N_EDGES + e];
        atomicAdd(&g_deg[c], 1);
    }
}

// ============================================================================
// Kernel 3: dinv = deg > 0 ? deg^-0.5 : 0
// ============================================================================
__global__ void k_dinv() {
    int i = blockIdx.x * blockDim.x + threadIdx.x;
    if (i < N_NODES) {
        int d = g_deg[i];
        g_dinv[i] = (d > 0) ? (1.0f / sqrtf((float)d)) : 0.0f;
    }
}

// ============================================================================
// Kernel 4: single-block exclusive scan of deg -> ptr
// ============================================================================
__global__ void k_scan() {
    __shared__ int part[1024];
    const int CH = (N_NODES + 1023) / 1024;   // 49
    int t = threadIdx.x;
    int base = t * CH;
    int s = 0;
    for (int i = 0; i < CH; i++) {
        int idx = base + i;
        if (idx < N_NODES) s += g_deg[idx];
    }
    part[t] = s;
    __syncthreads();
    // inclusive Hillis-Steele scan over 1024 partials
    for (int off = 1; off < 1024; off <<= 1) {
        int v = (t >= off) ? part[t - off] : 0;
        __syncthreads();
        part[t] += v;
        __syncthreads();
    }
    int ex = (t == 0) ? 0 : part[t - 1];
    for (int i = 0; i < CH; i++) {
        int idx = base + i;
        if (idx < N_NODES) { g_ptr[idx] = ex; ex += g_deg[idx]; }
    }
    if (t == 1023) g_ptr[N_NODES] = part[1023];
}

// ============================================================================
// Kernel 5: fill CSR (grouped by col). Also precompute norm per edge.
// ============================================================================
__global__ void k_fill(const int* __restrict__ ei) {
    int e = blockIdx.x * blockDim.x + threadIdx.x;
    if (e < N_EDGES) {
        int r = ei[e];
        int c = ei[N_EDGES + e];
        int pos = g_ptr[c] + atomicAdd(&g_cur[c], 1);
        g_srcs[pos]  = r;
        g_eids[pos]  = e;
        g_normv[pos] = g_dinv[r] * g_dinv[c];
    }
}

// ============================================================================
// Kernel 6: edge MLP stage 1, aggregated per target node.
//   hsum[v] = sum_{e into v} relu(concat(x[v], x[src], ea[e]) @ eW1 + eb1)
// one warp per node; lane owns 4 hidden units.
// ============================================================================
__global__ __launch_bounds__(256) void k_edge_mlp(
    const float* __restrict__ x, const float* __restrict__ ea,
    const float* __restrict__ eW1, const float* __restrict__ eb1)
{
    __shared__ float sW1[18 * H];       // 9216 B
    __shared__ float sb1[H];
    __shared__ float sm[8][20];         // per-warp message buffer

    int tid = threadIdx.x;
    #pragma unroll
    for (int i = 0; i < 9; i++) {
        int idx = tid + i * 256;
        if (idx < 18 * H) sW1[idx] = eW1[idx];
    }
    if (tid < H) sb1[tid] = eb1[tid];
    __syncthreads();

    int lid = tid & 31;
    int wlocal = tid >> 5;
    float* m = sm[wlocal];
    int gwarp  = (blockIdx.x * blockDim.x + tid) >> 5;
    int nwarps = (gridDim.x * blockDim.x) >> 5;

    float4 b = *(const float4*)&sb1[lid * 4];

    for (int v = gwarp; v < N_NODES; v += nwarps) {
        if (lid < NFEAT) m[lid] = x[v * NFEAT + lid];   // x_i = x[col]
        float a0 = 0.f, a1 = 0.f, a2 = 0.f, a3 = 0.f;
        int beg = g_ptr[v], end = g_ptr[v + 1];
        for (int e = beg; e < end; e++) {
            int s  = g_srcs[e];
            int id = g_eids[e];
            if (lid >= 7 && lid < 14)       m[lid] = x[s * NFEAT + (lid - 7)];
            else if (lid >= 14 && lid < 18) m[lid] = ea[id * EFEAT + (lid - 14)];
            __syncwarp();
            float d0 = b.x, d1 = b.y, d2 = b.z, d3 = b.w;
            #pragma unroll
            for (int j = 0; j < 18; j++) {
                float mj = m[j];
                float4 w = *(const float4*)&sW1[j * H + lid * 4];
                d0 += mj * w.x; d1 += mj * w.y; d2 += mj * w.z; d3 += mj * w.w;
            }
            a0 += fmaxf(d0, 0.f); a1 += fmaxf(d1, 0.f);
            a2 += fmaxf(d2, 0.f); a3 += fmaxf(d3, 0.f);
            __syncwarp();
        }
        float4 o; o.x = a0; o.y = a1; o.z = a2; o.w = a3;
        *(float4*)&g_hsum[(size_t)v * H + lid * 4] = o;
    }
}

// ============================================================================
// Kernel 7: GEMM  C[n,128] (+)= A[n,128] @ W[128,128]  (+ bias epilogue)
// 64 rows x 128 cols per block, 256 threads, 4x8 register tile per thread.
// ============================================================================
__global__ __launch_bounds__(256) void k_gemm128(
    const float* __restrict__ A, const float* __restrict__ W,
    float* __restrict__ C, const float* __restrict__ bias, int flags)
{
    __shared__ float Ws[32 * H];     // 16 KB: k-tile of W
    __shared__ float As[64 * 36];    // padded stride 36

    int tid = threadIdx.x;
    int tx = tid & 15;    // col group: cols tx*8 .. +7
    int ty = tid >> 4;    // row group: rows ty*4 .. +3
    int row0 = blockIdx.x * 64;

    float acc[4][8];
    #pragma unroll
    for (int i = 0; i < 4; i++)
        #pragma unroll
        for (int j = 0; j < 8; j++) acc[i][j] = 0.f;

    #pragma unroll
    for (int kt = 0; kt < 4; kt++) {
        // load W k-tile: 32x128 floats = 1024 float4
        const float4* Wg = (const float4*)(W + kt * 32 * H);
        float4* Wsv = (float4*)Ws;
        #pragma unroll
        for (int i = 0; i < 4; i++) Wsv[tid + i * 256] = Wg[tid + i * 256];
        // load A tile: 64 rows x 32 cols = 512 float4
        #pragma unroll
        for (int i = 0; i < 2; i++) {
            int idx = tid + i * 256;
            int r = idx >> 3;
            int c4 = idx & 7;
            float4 v = make_float4(0.f, 0.f, 0.f, 0.f);
            if (row0 + r < N_NODES)
                v = *(const float4*)(A + (size_t)(row0 + r) * H + kt * 32 + c4 * 4);
            *(float4*)&As[r * 36 + c4 * 4] = v;
        }
        __syncthreads();

        #pragma unroll 16
        for (int k = 0; k < 32; k++) {
            float a0 = As[(ty * 4 + 0) * 36 + k];
            float a1 = As[(ty * 4 + 1) * 36 + k];
            float a2 = As[(ty * 4 + 2) * 36 + k];
            float a3 = As[(ty * 4 + 3) * 36 + k];
            float4 b0 = *(const float4*)&Ws[k * H + tx * 8];
            float4 b1 = *(const float4*)&Ws[k * H + tx * 8 + 4];
            float bb[8] = {b0.x, b0.y, b0.z, b0.w, b1.x, b1.y, b1.z, b1.w};
            #pragma unroll
            for (int j = 0; j < 8; j++) {
                acc[0][j] += a0 * bb[j];
                acc[1][j] += a1 * bb[j];
                acc[2][j] += a2 * bb[j];
                acc[3][j] += a3 * bb[j];
            }
        }
        __syncthreads();
    }

    // epilogue
    #pragma unroll
    for (int i = 0; i < 4; i++) {
        int r = row0 + ty * 4 + i;
        if (r >= N_NODES) continue;
        float* cp = C + (size_t)r * H + tx * 8;
        float degs = 1.0f;
        if (flags & FLAG_DEGSCALE) degs = (float)g_deg[r];
        #pragma unroll
        for (int j = 0; j < 8; j++) {
            float v = acc[i][j];
            if (flags & FLAG_ACCUM) v += cp[j];
            if (flags & FLAG_BIAS)  v += bias[tx * 8 + j] * degs;
            if (flags & FLAG_RELU)  v = fmaxf(v, 0.f);
            cp[j] = v;
        }
    }
}

// ============================================================================
// Kernel 8: SpMM hop:  PN[v] = sum_{e into v} norm[e] * P[src[e]]
// one warp per node, lane owns 4 features (float4).
// ============================================================================
__global__ __launch_bounds__(256) void k_spmm(
    const float* __restrict__ P, float* __restrict__ PN)
{
    int tid = threadIdx.x;
    int lid = tid & 31;
    int gwarp  = (blockIdx.x * blockDim.x + tid) >> 5;
    int nwarps = (gridDim.x * blockDim.x) >> 5;

    for (int v = gwarp; v < N_NODES; v += nwarps) {
        float a0 = 0.f, a1 = 0.f, a2 = 0.f, a3 = 0.f;
        int beg = g_ptr[v], end = g_ptr[v + 1];
        for (int e = beg; e < end; e++) {
            int s = g_srcs[e];
            float w = g_normv[e];
            float4 val = *(const float4*)&P[(size_t)s * H + lid * 4];
            a0 += w * val.x; a1 += w * val.y; a2 += w * val.z; a3 += w * val.w;
        }
        float4 o; o.x = a0; o.y = a1; o.z = a2; o.w = a3;
        *(float4*)&PN[(size_t)v * H + lid * 4] = o;
    }
}

// ============================================================================
// Kernel 9: output projection  y[n, 0..1] = h[n] @ out_W + out_b
// one warp per node, warp reduction.
// ============================================================================
__global__ __launch_bounds__(256) void k_out(
    const float* __restrict__ Hf, const float* __restrict__ oW,
    const float* __restrict__ ob, float* __restrict__ y)
{
    int tid = threadIdx.x;
    int lid = tid & 31;
    int gwarp  = (blockIdx.x * blockDim.x + tid) >> 5;
    int nwarps = (gridDim.x * blockDim.x) >> 5;

    for (int v = gwarp; v < N_NODES; v += nwarps) {
        float4 hv = *(const float4*)&Hf[(size_t)v * H + lid * 4];
        float s0 = 0.f, s1 = 0.f;
        #pragma unroll
        for (int i = 0; i < 4; i++) {
            float hh = (i == 0) ? hv.x : (i == 1) ? hv.y : (i == 2) ? hv.z : hv.w;
            int j = lid * 4 + i;
            s0 += hh * oW[j * 2 + 0];
            s1 += hh * oW[j * 2 + 1];
        }
        #pragma unroll
        for (int o = 16; o > 0; o >>= 1) {
            s0 += __shfl_xor_sync(0xFFFFFFFFu, s0, o);
            s1 += __shfl_xor_sync(0xFFFFFFFFu, s1, o);
        }
        if (lid == 0) {
            y[(size_t)v * 2 + 0] = s0 + ob[0];
            y[(size_t)v * 2 + 1] = s1 + ob[1];
        }
    }
}

// ============================================================================
// Host launcher
// ============================================================================
extern "C" void kernel_launch(void* const* d_in, const int* in_sizes, int n_in,
                              void* d_out, int out_size)
{
    const float* x    = (const float*)d_in[0];
    const int*   ei   = (const int*)  d_in[1];
    const float* ea   = (const float*)d_in[2];
    const float* eW1  = (const float*)d_in[3];
    const float* eb1  = (const float*)d_in[4];
    const float* eW2  = (const float*)d_in[5];
    const float* eb2  = (const float*)d_in[6];
    const float* tagW = (const float*)d_in[7];
    const float* tagb = (const float*)d_in[8];
    const float* outW = (const float*)d_in[9];
    const float* outb = (const float*)d_in[10];
    float* y = (float*)d_out;

    float *hsum, *bufA, *bufB, *p0, *p1;
    cudaGetSymbolAddress((void**)&hsum, g_hsum);
    cudaGetSymbolAddress((void**)&bufA, g_bufA);
    cudaGetSymbolAddress((void**)&bufB, g_bufB);
    cudaGetSymbolAddress((void**)&p0,   g_p0);
    cudaGetSymbolAddress((void**)&p1,   g_p1);

    const int NB_N  = (N_NODES + 255) / 256;
    const int NB_E  = (N_EDGES + 255) / 256;
    const int NB_G  = (N_NODES + 63) / 64;     // gemm blocks
    const int NB_W  = (N_NODES + 7) / 8;       // one warp per node, 8 warps/block

    k_init <<<NB_N, 256>>>();
    k_count<<<NB_E, 256>>>(ei);
    k_dinv <<<NB_N, 256>>>();
    k_scan <<<1, 1024>>>();
    k_fill <<<NB_E, 256>>>(ei);

    k_edge_mlp<<<2048, 256>>>(x, ea, eW1, eb1);

    // h = hsum @ eW2 + deg * eb2
    k_gemm128<<<NB_G, 256>>>(hsum, eW2, bufA, eb2, FLAG_BIAS | FLAG_DEGSCALE);

    float* h   = bufA;
    float* out = bufB;
    for (int l = 0; l < L_LAYERS; l++) {
        const float* Wl = tagW + (size_t)l * (K_HOPS + 1) * H * H;
        k_gemm128<<<NB_G, 256>>>(h, Wl, out, nullptr, 0);
        const float* p = h;
        for (int k = 1; k <= K_HOPS; k++) {
            float* pn = (k & 1) ? p0 : p1;
            k_spmm<<<NB_W, 256>>>(p, pn);
            int fl = FLAG_ACCUM;
            const float* bias = nullptr;
            if (k == K_HOPS) {
                fl |= FLAG_BIAS;
                bias = tagb + (size_t)l * H;
                if (l < L_LAYERS - 1) fl |= FLAG_RELU;
            }
            k_gemm128<<<NB_G, 256>>>(pn, Wl + (size_t)k * H * H, out, bias, fl);
            p = pn;
        }
        float* tmp = h; h = out; out = tmp;
    }

    k_out<<<NB_W, 256>>>(h, outW, outb, y);
}